// round 11
// baseline (speedup 1.0000x reference)
#include <cuda_runtime.h>
#include <cuda_bf16.h>
#include <cstdint>

// MemoryTemporalBlock — bf16 m16n8k16, GG=4, zero-waste m-tiling, 2 CTAs/SM.
// One CTA per 4 (b,n) tiles (M=48 = 3 m16-tiles), 256 threads, ~101KB smem.
// x, Q, K, V, attn-out all stored packed bf16 in smem; residual re-read from
// gmem in the LN epilogue; pre-LN fp32 buffer overlays the K/V bf16 buffers.

#define TT 12
#define DD 256
#define GG 4
#define MROWS (GG * TT)   // 48
#define LDPH 132          // bf16 buffer stride in uints (bf16x2)
#define LDPF 260          // fp32 pre-LN stride (floats)
#define MMM 8
#define LOG2E 1.4426950408889634f

// Wfrag[mat][wn(8)][kstep(16)][ntile(4)][lane(32)] as uint2 (4 bf16)
__device__ uint2 g_Wfrag[4][8][16][4][32];

static __device__ __forceinline__ uint32_t pkbf(float lo, float hi) {
    __nv_bfloat162 h = __float22bfloat162_rn(make_float2(lo, hi));
    uint32_t r; memcpy(&r, &h, 4); return r;
}
static __device__ __forceinline__ float4 upk4(uint2 u) {
    __nv_bfloat162 a, b; memcpy(&a, &u.x, 4); memcpy(&b, &u.y, 4);
    float2 fa = __bfloat1622float2(a), fb = __bfloat1622float2(b);
    return make_float4(fa.x, fa.y, fb.x, fb.y);
}
static __device__ __forceinline__ float ex2(float x) {
    float r; asm("ex2.approx.f32 %0, %1;" : "=f"(r) : "f"(x)); return r;
}
static __device__ __forceinline__ void mma_bf16(float* c, const uint32_t* a,
                                                uint32_t b0, uint32_t b1) {
    asm("mma.sync.aligned.m16n8k16.row.col.f32.bf16.bf16.f32 "
        "{%0,%1,%2,%3}, {%4,%5,%6,%7}, {%8,%9}, {%0,%1,%2,%3};"
        : "+f"(c[0]), "+f"(c[1]), "+f"(c[2]), "+f"(c[3])
        : "r"(a[0]), "r"(a[1]), "r"(a[2]), "r"(a[3]), "r"(b0), "r"(b1));
}
static __device__ __forceinline__ float warp_sum(float v) {
#pragma unroll
    for (int o = 16; o; o >>= 1) v += __shfl_xor_sync(0xffffffffu, v, o);
    return v;
}
static __device__ __forceinline__ float gsum8(float v, unsigned m) {
    v += __shfl_xor_sync(m, v, 1);
    v += __shfl_xor_sync(m, v, 2);
    v += __shfl_xor_sync(m, v, 4);
    return v;
}

__global__ void prep_kernel(const float* __restrict__ wq, const float* __restrict__ wk,
                            const float* __restrict__ wv, const float* __restrict__ wf)
{
    int i = blockIdx.x * blockDim.x + threadIdx.x;   // 65536 threads
    int lane = i & 31;
    int nt   = (i >> 5) & 3;
    int kk   = (i >> 7) & 15;
    int wn   = (i >> 11) & 7;
    int mat  = i >> 14;
    const float* W = (mat == 0) ? wq : (mat == 1) ? wk : (mat == 2) ? wv : wf;
    int e = wn * 32 + nt * 8 + (lane >> 2);
    int d = kk * 16 + (lane & 3) * 2;
    uint2 v;
    v.x = pkbf(__ldg(W + e * DD + d),     __ldg(W + e * DD + d + 1));
    v.y = pkbf(__ldg(W + e * DD + d + 8), __ldg(W + e * DD + d + 9));
    g_Wfrag[mat][wn][kk][nt][lane] = v;
}

// Single-matrix GEMM sweep over K=256; A = packed bf16 smem, 3 m-tiles (M=48).
static __device__ __forceinline__ void gemm_sweep(
    const uint32_t* __restrict__ As, int lane,
    const uint2* __restrict__ Bp,
    float acc[3][4][4])
{
#pragma unroll
    for (int mt = 0; mt < 3; mt++)
#pragma unroll
        for (int nt = 0; nt < 4; nt++)
#pragma unroll
            for (int j = 0; j < 4; j++) acc[mt][nt][j] = 0.f;

    uint2 b0[4], b1[4];
#pragma unroll
    for (int nt = 0; nt < 4; nt++) {
        b0[nt] = __ldg(Bp + nt * 32 + lane);
        b1[nt] = __ldg(Bp + (4 + nt) * 32 + lane);
    }

    const int r0 = lane >> 2, c0 = lane & 3;
#pragma unroll 2
    for (int kk = 0; kk < 16; kk++) {
        uint32_t a[3][4];
#pragma unroll
        for (int mt = 0; mt < 3; mt++) {
            const uint32_t* p = As + (mt * 16 + r0) * LDPH + kk * 8 + c0;
            a[mt][0] = p[0];
            a[mt][1] = p[8 * LDPH];
            a[mt][2] = p[4];
            a[mt][3] = p[8 * LDPH + 4];
        }
        uint2 bc[4];
#pragma unroll
        for (int nt = 0; nt < 4; nt++) { bc[nt] = b0[nt]; b0[nt] = b1[nt]; }
        if (kk < 14) {
#pragma unroll
            for (int nt = 0; nt < 4; nt++)
                b1[nt] = __ldg(Bp + ((kk + 2) * 4 + nt) * 32 + lane);
        }
#pragma unroll
        for (int nt = 0; nt < 4; nt++)
#pragma unroll
            for (int mt = 0; mt < 3; mt++)
                mma_bf16(acc[mt][nt], a[mt], bc[nt].x, bc[nt].y);
    }
}

// Store accumulators (+bias) as packed bf16 into a [48][LDPH] buffer.
static __device__ __forceinline__ void store_accb(
    uint32_t* __restrict__ dst, const float* __restrict__ bias,
    int w, int lane, const float acc[3][4][4])
{
#pragma unroll
    for (int nt = 0; nt < 4; nt++) {
        const int col = w * 32 + nt * 8 + 2 * (lane & 3);
        const float2 cb = __ldg((const float2*)(bias + col));
        const int cu = col >> 1;
#pragma unroll
        for (int mt = 0; mt < 3; mt++) {
            const int r0 = mt * 16 + (lane >> 2);
#pragma unroll
            for (int h2 = 0; h2 < 2; h2++) {
                const int r = r0 + 8 * h2;
                dst[r * LDPH + cu] =
                    pkbf(acc[mt][nt][2 * h2] + cb.x, acc[mt][nt][2 * h2 + 1] + cb.y);
            }
        }
    }
}

__global__ void __launch_bounds__(256, 2)
mtb_kernel(const float* __restrict__ x,
           const float* __restrict__ bq, const float* __restrict__ bk,
           const float* __restrict__ bv,
           const float* __restrict__ memk, const float* __restrict__ memv,
           const float* __restrict__ bf,
           const float* __restrict__ gamma, const float* __restrict__ beta,
           const float* __restrict__ alpha_p,
           float* __restrict__ out)
{
    extern __shared__ uint32_t smu[];
    uint32_t* xb = smu;                     // bf16 x            [48][132]
    uint32_t* qb = smu + 1 * MROWS * LDPH;  // bf16 Q -> attn out
    uint32_t* kb = smu + 2 * MROWS * LDPH;  // bf16 K
    uint32_t* vb = smu + 3 * MROWS * LDPH;  // bf16 V
    float*   pre = (float*)kb;              // fp32 pre-LN (overlays K,V after attention)

    const int tid  = threadIdx.x;
    const int w    = tid >> 5;
    const int lane = tid & 31;
    const size_t gbase = (size_t)blockIdx.x * (MROWS * DD);

    // ---- stage x as packed bf16 ----
    {
        const float4* xg = (const float4*)(x + gbase);
#pragma unroll
        for (int p = 0; p < 12; p++) {
            const int idx = p * 256 + tid;          // float4 index, 3072 total
            const int r = idx >> 6, cg = idx & 63;
            const float4 xv = xg[idx];
            xb[r * LDPH + cg * 2]     = pkbf(xv.x, xv.y);
            xb[r * LDPH + cg * 2 + 1] = pkbf(xv.z, xv.w);
        }
    }
    __syncthreads();

    // ---- sweeps: Q, K, V ----
    {
        float acc[3][4][4];
        gemm_sweep(xb, lane, &g_Wfrag[0][w][0][0][0], acc);
        store_accb(qb, bq, w, lane, acc);
        gemm_sweep(xb, lane, &g_Wfrag[1][w][0][0][0], acc);
        store_accb(kb, bk, w, lane, acc);
        gemm_sweep(xb, lane, &g_Wfrag[2][w][0][0][0], acc);
        store_accb(vb, bv, w, lane, acc);
    }
    __syncthreads();

    // ---- attention: 32 units (tile,head); warp w -> units 4w..4w+3 ----
    // lane split: rep = lane>>3 owns t in {rep,rep+4,rep+8}; sub = lane&7 owns 4 dk.
    const float sl = 0.17677669529663687f * LOG2E;
    const float wl = 1.f / (1.f + __expf(-__ldg(alpha_p)));
    const float wt = 1.f - wl;
    const int rep = lane >> 3;
    const int sub = lane & 7;
    const unsigned gmask = 0xFFu << (8 * rep);

#pragma unroll
    for (int u = 0; u < 4; u++) {
        const int unit = w * 4 + u;
        const int tau = unit >> 3, h = unit & 7;
        const int rb = tau * TT;
        const int cu = h * 16 + sub * 2;        // uint col in bf16 buffers

        float4 qv[3]; float4 ao[3]; float dn[3];
        float4 al[3]; float dml[3];
#pragma unroll
        for (int i = 0; i < 3; i++) {
            const float4 q = upk4(*(const uint2*)(qb + (rb + rep + 4 * i) * LDPH + cu));
            qv[i] = make_float4(q.x * sl, q.y * sl, q.z * sl, q.w * sl);
            ao[i] = make_float4(0.f, 0.f, 0.f, 0.f);
            al[i] = make_float4(0.f, 0.f, 0.f, 0.f);
            dn[i] = 0.f; dml[i] = 0.f;
        }
        // causal temporal attention
#pragma unroll
        for (int s = 0; s < TT; s++) {
            const float4 kv = upk4(*(const uint2*)(kb + (rb + s) * LDPH + cu));
            const float4 vv = upk4(*(const uint2*)(vb + (rb + s) * LDPH + cu));
#pragma unroll
            for (int i = 0; i < 3; i++) {
                const int t = rep + 4 * i;
                if (t >= s) {
                    float p = fmaf(qv[i].x, kv.x, fmaf(qv[i].y, kv.y,
                              fmaf(qv[i].z, kv.z, qv[i].w * kv.w)));
                    p = gsum8(p, gmask);
                    const float wg = ex2(p);
                    dn[i] += wg;
                    ao[i].x = fmaf(wg, vv.x, ao[i].x);
                    ao[i].y = fmaf(wg, vv.y, ao[i].y);
                    ao[i].z = fmaf(wg, vv.z, ao[i].z);
                    ao[i].w = fmaf(wg, vv.w, ao[i].w);
                }
            }
        }
        // memory-bank attention (fp32 from gmem/L2)
#pragma unroll
        for (int m = 0; m < MMM; m++) {
            const float4 mk = __ldg((const float4*)(memk + (h * MMM + m) * 32 + sub * 4));
            const float4 mv = __ldg((const float4*)(memv + (h * MMM + m) * 32 + sub * 4));
#pragma unroll
            for (int i = 0; i < 3; i++) {
                float p = fmaf(qv[i].x, mk.x, fmaf(qv[i].y, mk.y,
                          fmaf(qv[i].z, mk.z, qv[i].w * mk.w)));
                p = gsum8(p, gmask);
                const float wg = ex2(p);
                dml[i] += wg;
                al[i].x = fmaf(wg, mv.x, al[i].x);
                al[i].y = fmaf(wg, mv.y, al[i].y);
                al[i].z = fmaf(wg, mv.z, al[i].z);
                al[i].w = fmaf(wg, mv.w, al[i].w);
            }
        }
        // gate + store packed bf16 back into qb (this unit's own region)
#pragma unroll
        for (int i = 0; i < 3; i++) {
            const float id = wt / dn[i], il = wl / dml[i];
            const int r = rb + rep + 4 * i;
            qb[r * LDPH + cu] =
                pkbf(ao[i].x * id + al[i].x * il, ao[i].y * id + al[i].y * il);
            qb[r * LDPH + cu + 1] =
                pkbf(ao[i].z * id + al[i].z * il, ao[i].w * id + al[i].w * il);
        }
    }
    __syncthreads();

    // ---- sweep: fc; epilogue writes fp32 (acc+bias) into pre (overlays K/V) ----
    {
        float acc[3][4][4];
        gemm_sweep(qb, lane, &g_Wfrag[3][w][0][0][0], acc);
#pragma unroll
        for (int nt = 0; nt < 4; nt++) {
            const int col = w * 32 + nt * 8 + 2 * (lane & 3);
            const float2 cbf = __ldg((const float2*)(bf + col));
#pragma unroll
            for (int mt = 0; mt < 3; mt++) {
                const int r0 = mt * 16 + (lane >> 2);
#pragma unroll
                for (int h2 = 0; h2 < 2; h2++) {
                    const int r = r0 + 8 * h2;
                    *(float2*)(pre + r * LDPF + col) =
                        make_float2(acc[mt][nt][2 * h2] + cbf.x,
                                    acc[mt][nt][2 * h2 + 1] + cbf.y);
                }
            }
        }
    }
    __syncthreads();

    // ---- LayerNorm: 6 rows per warp; residual x re-read from gmem (coalesced) ----
    for (int r = w * 6; r < w * 6 + 6; r++) {
        const float* row  = pre + r * LDPF;
        const float* xrow = x + gbase + (size_t)r * DD;
        float vals[8];
        float s = 0.f, s2 = 0.f;
#pragma unroll
        for (int j = 0; j < 8; j++) {
            const float val = row[lane + 32 * j] + __ldg(xrow + lane + 32 * j);
            vals[j] = val;
            s += val; s2 = fmaf(val, val, s2);
        }
        s = warp_sum(s); s2 = warp_sum(s2);
        const float mu = s * (1.f / 256.f);
        const float var = s2 * (1.f / 256.f) - mu * mu;
        const float inv = rsqrtf(var + 1e-5f);
        float* orow = out + gbase + (size_t)r * DD;
#pragma unroll
        for (int j = 0; j < 8; j++) {
            const int c = lane + 32 * j;
            orow[c] = (vals[j] - mu) * inv * __ldg(gamma + c) + __ldg(beta + c);
        }
    }
}

extern "C" void kernel_launch(void* const* d_in, const int* in_sizes, int n_in,
                              void* d_out, int out_size)
{
    (void)in_sizes; (void)n_in; (void)out_size;
    const float* x     = (const float*)d_in[0];
    const float* Wq_w  = (const float*)d_in[1];
    const float* Wq_b  = (const float*)d_in[2];
    const float* Wk_w  = (const float*)d_in[3];
    const float* Wk_b  = (const float*)d_in[4];
    const float* Wv_w  = (const float*)d_in[5];
    const float* Wv_b  = (const float*)d_in[6];
    const float* mem_k = (const float*)d_in[7];
    const float* mem_v = (const float*)d_in[8];
    const float* fc_w  = (const float*)d_in[9];
    const float* fc_b  = (const float*)d_in[10];
    const float* gamma = (const float*)d_in[11];
    const float* beta  = (const float*)d_in[12];
    const float* alpha = (const float*)d_in[13];
    float* out = (float*)d_out;

    // 4 bf16 buffers [48][132] uints = 101376 B (pre-LN fp32 overlays kb+vb)
    const int smemBytes = 4 * MROWS * LDPH * (int)sizeof(uint32_t);
    cudaFuncSetAttribute(mtb_kernel, cudaFuncAttributeMaxDynamicSharedMemorySize, smemBytes);

    prep_kernel<<<256, 256>>>(Wq_w, Wk_w, Wv_w, fc_w);
    mtb_kernel<<<16384 / GG, 256, smemBytes>>>(x, Wq_b, Wk_b, Wv_b, mem_k, mem_v,
                                               fc_b, gamma, beta, alpha, out);
}

// round 12
// speedup vs baseline: 1.5708x; 1.5708x over previous
#include <cuda_runtime.h>
#include <cuda_bf16.h>
#include <cstdint>

// MemoryTemporalBlock — bf16 m16n8k16 + ldmatrix, GG=4 zero-waste tiling.
// One CTA per 4 (b,n) tiles (M=48 = 3 m16-tiles), 256 threads, ~101KB smem,
// 2 CTAs/SM. A-fragments loaded via ldmatrix.m8n8.x4; x/Q/K/V/attn-out packed
// bf16 in smem; fc epilogue fp32 overlays K/V; residual re-read from gmem.

#define TT 12
#define DD 256
#define GG 4
#define MROWS (GG * TT)   // 48
#define LDPH 132          // bf16 buffer stride in uints (bf16x2)
#define LDPF 260          // fp32 pre-LN stride (floats)
#define MMM 8
#define LOG2E 1.4426950408889634f

// Wfrag[mat][wn(8)][kstep(16)][ntile(4)][lane(32)] as uint2 (4 bf16)
__device__ uint2 g_Wfrag[4][8][16][4][32];

static __device__ __forceinline__ uint32_t pkbf(float lo, float hi) {
    __nv_bfloat162 h = __float22bfloat162_rn(make_float2(lo, hi));
    uint32_t r; memcpy(&r, &h, 4); return r;
}
static __device__ __forceinline__ float4 upk4(uint2 u) {
    __nv_bfloat162 a, b; memcpy(&a, &u.x, 4); memcpy(&b, &u.y, 4);
    float2 fa = __bfloat1622float2(a), fb = __bfloat1622float2(b);
    return make_float4(fa.x, fa.y, fb.x, fb.y);
}
static __device__ __forceinline__ float ex2(float x) {
    float r; asm("ex2.approx.f32 %0, %1;" : "=f"(r) : "f"(x)); return r;
}
static __device__ __forceinline__ void ldsm4(uint32_t* a, uint32_t saddr) {
    asm volatile("ldmatrix.sync.aligned.m8n8.x4.shared.b16 {%0,%1,%2,%3}, [%4];"
        : "=r"(a[0]), "=r"(a[1]), "=r"(a[2]), "=r"(a[3]) : "r"(saddr));
}
static __device__ __forceinline__ void mma_bf16(float* c, const uint32_t* a,
                                                uint32_t b0, uint32_t b1) {
    asm("mma.sync.aligned.m16n8k16.row.col.f32.bf16.bf16.f32 "
        "{%0,%1,%2,%3}, {%4,%5,%6,%7}, {%8,%9}, {%0,%1,%2,%3};"
        : "+f"(c[0]), "+f"(c[1]), "+f"(c[2]), "+f"(c[3])
        : "r"(a[0]), "r"(a[1]), "r"(a[2]), "r"(a[3]), "r"(b0), "r"(b1));
}
static __device__ __forceinline__ float warp_sum(float v) {
#pragma unroll
    for (int o = 16; o; o >>= 1) v += __shfl_xor_sync(0xffffffffu, v, o);
    return v;
}
static __device__ __forceinline__ float gsum8(float v, unsigned m) {
    v += __shfl_xor_sync(m, v, 1);
    v += __shfl_xor_sync(m, v, 2);
    v += __shfl_xor_sync(m, v, 4);
    return v;
}

__global__ void prep_kernel(const float* __restrict__ wq, const float* __restrict__ wk,
                            const float* __restrict__ wv, const float* __restrict__ wf)
{
    int i = blockIdx.x * blockDim.x + threadIdx.x;   // 65536 threads
    int lane = i & 31;
    int nt   = (i >> 5) & 3;
    int kk   = (i >> 7) & 15;
    int wn   = (i >> 11) & 7;
    int mat  = i >> 14;
    const float* W = (mat == 0) ? wq : (mat == 1) ? wk : (mat == 2) ? wv : wf;
    int e = wn * 32 + nt * 8 + (lane >> 2);
    int d = kk * 16 + (lane & 3) * 2;
    uint2 v;
    v.x = pkbf(__ldg(W + e * DD + d),     __ldg(W + e * DD + d + 1));
    v.y = pkbf(__ldg(W + e * DD + d + 8), __ldg(W + e * DD + d + 9));
    g_Wfrag[mat][wn][kk][nt][lane] = v;
}

// GEMM sweep over K=256; A = packed bf16 smem (shared addr), 3 m-tiles (M=48).
static __device__ __forceinline__ void gemm_sweep(
    uint32_t abase, int lane,
    const uint2* __restrict__ Bp,
    float acc[3][4][4])
{
#pragma unroll
    for (int mt = 0; mt < 3; mt++)
#pragma unroll
        for (int nt = 0; nt < 4; nt++)
#pragma unroll
            for (int j = 0; j < 4; j++) acc[mt][nt][j] = 0.f;

    uint2 b0[4], b1[4];
#pragma unroll
    for (int nt = 0; nt < 4; nt++) {
        b0[nt] = __ldg(Bp + nt * 32 + lane);
        b1[nt] = __ldg(Bp + (4 + nt) * 32 + lane);
    }

    // per-lane ldmatrix base: lanes 0-7 -> rows 0-7 (k lo), 8-15 -> rows 8-15 (k lo),
    // 16-23 -> rows 0-7 (k hi), 24-31 -> rows 8-15 (k hi)
    const int arow = (lane & 7) + ((lane >> 3) & 1) * 8;
    const uint32_t alane = abase + (uint32_t)(arow * LDPH * 4) + ((lane >> 4) * 16);

#pragma unroll 4
    for (int kk = 0; kk < 16; kk++) {
        uint32_t a[3][4];
#pragma unroll
        for (int mt = 0; mt < 3; mt++)
            ldsm4(a[mt], alane + (uint32_t)(mt * 16 * LDPH * 4) + (uint32_t)(kk * 32));
        uint2 bc[4];
#pragma unroll
        for (int nt = 0; nt < 4; nt++) { bc[nt] = b0[nt]; b0[nt] = b1[nt]; }
        if (kk < 14) {
#pragma unroll
            for (int nt = 0; nt < 4; nt++)
                b1[nt] = __ldg(Bp + ((kk + 2) * 4 + nt) * 32 + lane);
        }
#pragma unroll
        for (int nt = 0; nt < 4; nt++)
#pragma unroll
            for (int mt = 0; mt < 3; mt++)
                mma_bf16(acc[mt][nt], a[mt], bc[nt].x, bc[nt].y);
    }
}

// Store accumulators (+bias) as packed bf16 into a [48][LDPH] buffer.
static __device__ __forceinline__ void store_accb(
    uint32_t* __restrict__ dst, const float* __restrict__ bias,
    int w, int lane, const float acc[3][4][4])
{
#pragma unroll
    for (int nt = 0; nt < 4; nt++) {
        const int col = w * 32 + nt * 8 + 2 * (lane & 3);
        const float2 cb = __ldg((const float2*)(bias + col));
        const int cu = col >> 1;
#pragma unroll
        for (int mt = 0; mt < 3; mt++) {
            const int r0 = mt * 16 + (lane >> 2);
#pragma unroll
            for (int h2 = 0; h2 < 2; h2++) {
                const int r = r0 + 8 * h2;
                dst[r * LDPH + cu] =
                    pkbf(acc[mt][nt][2 * h2] + cb.x, acc[mt][nt][2 * h2 + 1] + cb.y);
            }
        }
    }
}

__global__ void __launch_bounds__(256, 2)
mtb_kernel(const float* __restrict__ x,
           const float* __restrict__ bq, const float* __restrict__ bk,
           const float* __restrict__ bv,
           const float* __restrict__ memk, const float* __restrict__ memv,
           const float* __restrict__ bf,
           const float* __restrict__ gamma, const float* __restrict__ beta,
           const float* __restrict__ alpha_p,
           float* __restrict__ out)
{
    extern __shared__ uint32_t smu[];
    uint32_t* xb = smu;                     // bf16 x            [48][132]
    uint32_t* qb = smu + 1 * MROWS * LDPH;  // bf16 Q -> attn out
    uint32_t* kb = smu + 2 * MROWS * LDPH;  // bf16 K
    uint32_t* vb = smu + 3 * MROWS * LDPH;  // bf16 V
    float*   pre = (float*)kb;              // fp32 pre-LN (overlays K,V after attention)

    const uint32_t xb_s = (uint32_t)__cvta_generic_to_shared(xb);
    const uint32_t qb_s = (uint32_t)__cvta_generic_to_shared(qb);

    const int tid  = threadIdx.x;
    const int w    = tid >> 5;
    const int lane = tid & 31;
    const size_t gbase = (size_t)blockIdx.x * (MROWS * DD);

    // ---- stage x as packed bf16 ----
    {
        const float4* xg = (const float4*)(x + gbase);
#pragma unroll
        for (int p = 0; p < 12; p++) {
            const int idx = p * 256 + tid;          // float4 index, 3072 total
            const int r = idx >> 6, cg = idx & 63;
            const float4 xv = xg[idx];
            xb[r * LDPH + cg * 2]     = pkbf(xv.x, xv.y);
            xb[r * LDPH + cg * 2 + 1] = pkbf(xv.z, xv.w);
        }
    }
    __syncthreads();

    // ---- sweeps: Q, K, V ----
    {
        float acc[3][4][4];
        gemm_sweep(xb_s, lane, &g_Wfrag[0][w][0][0][0], acc);
        store_accb(qb, bq, w, lane, acc);
        gemm_sweep(xb_s, lane, &g_Wfrag[1][w][0][0][0], acc);
        store_accb(kb, bk, w, lane, acc);
        gemm_sweep(xb_s, lane, &g_Wfrag[2][w][0][0][0], acc);
        store_accb(vb, bv, w, lane, acc);
    }
    __syncthreads();

    // ---- attention: 32 units (tile,head); warp w -> units 4w..4w+3 ----
    const float sl = 0.17677669529663687f * LOG2E;
    const float wl = 1.f / (1.f + __expf(-__ldg(alpha_p)));
    const float wt = 1.f - wl;
    const int rep = lane >> 3;
    const int sub = lane & 7;
    const unsigned gmask = 0xFFu << (8 * rep);

#pragma unroll
    for (int u = 0; u < 4; u++) {
        const int unit = w * 4 + u;
        const int tau = unit >> 3, h = unit & 7;
        const int rb = tau * TT;
        const int cu = h * 16 + sub * 2;        // uint col in bf16 buffers

        float4 qv[3]; float4 ao[3]; float dn[3];
        float4 al[3]; float dml[3];
#pragma unroll
        for (int i = 0; i < 3; i++) {
            const float4 q = upk4(*(const uint2*)(qb + (rb + rep + 4 * i) * LDPH + cu));
            qv[i] = make_float4(q.x * sl, q.y * sl, q.z * sl, q.w * sl);
            ao[i] = make_float4(0.f, 0.f, 0.f, 0.f);
            al[i] = make_float4(0.f, 0.f, 0.f, 0.f);
            dn[i] = 0.f; dml[i] = 0.f;
        }
        // causal temporal attention
#pragma unroll
        for (int s = 0; s < TT; s++) {
            const float4 kv = upk4(*(const uint2*)(kb + (rb + s) * LDPH + cu));
            const float4 vv = upk4(*(const uint2*)(vb + (rb + s) * LDPH + cu));
#pragma unroll
            for (int i = 0; i < 3; i++) {
                const int t = rep + 4 * i;
                if (t >= s) {
                    float p = fmaf(qv[i].x, kv.x, fmaf(qv[i].y, kv.y,
                              fmaf(qv[i].z, kv.z, qv[i].w * kv.w)));
                    p = gsum8(p, gmask);
                    const float wg = ex2(p);
                    dn[i] += wg;
                    ao[i].x = fmaf(wg, vv.x, ao[i].x);
                    ao[i].y = fmaf(wg, vv.y, ao[i].y);
                    ao[i].z = fmaf(wg, vv.z, ao[i].z);
                    ao[i].w = fmaf(wg, vv.w, ao[i].w);
                }
            }
        }
        // memory-bank attention (fp32 from gmem/L2)
#pragma unroll
        for (int m = 0; m < MMM; m++) {
            const float4 mk = __ldg((const float4*)(memk + (h * MMM + m) * 32 + sub * 4));
            const float4 mv = __ldg((const float4*)(memv + (h * MMM + m) * 32 + sub * 4));
#pragma unroll
            for (int i = 0; i < 3; i++) {
                float p = fmaf(qv[i].x, mk.x, fmaf(qv[i].y, mk.y,
                          fmaf(qv[i].z, mk.z, qv[i].w * mk.w)));
                p = gsum8(p, gmask);
                const float wg = ex2(p);
                dml[i] += wg;
                al[i].x = fmaf(wg, mv.x, al[i].x);
                al[i].y = fmaf(wg, mv.y, al[i].y);
                al[i].z = fmaf(wg, mv.z, al[i].z);
                al[i].w = fmaf(wg, mv.w, al[i].w);
            }
        }
        // gate + store packed bf16 back into qb (this unit's own region)
#pragma unroll
        for (int i = 0; i < 3; i++) {
            const float id = wt / dn[i], il = wl / dml[i];
            const int r = rb + rep + 4 * i;
            qb[r * LDPH + cu] =
                pkbf(ao[i].x * id + al[i].x * il, ao[i].y * id + al[i].y * il);
            qb[r * LDPH + cu + 1] =
                pkbf(ao[i].z * id + al[i].z * il, ao[i].w * id + al[i].w * il);
        }
    }
    __syncthreads();

    // ---- sweep: fc; epilogue writes fp32 (acc+bias) into pre (overlays K/V) ----
    {
        float acc[3][4][4];
        gemm_sweep(qb_s, lane, &g_Wfrag[3][w][0][0][0], acc);
#pragma unroll
        for (int nt = 0; nt < 4; nt++) {
            const int col = w * 32 + nt * 8 + 2 * (lane & 3);
            const float2 cbf = __ldg((const float2*)(bf + col));
#pragma unroll
            for (int mt = 0; mt < 3; mt++) {
                const int r0 = mt * 16 + (lane >> 2);
#pragma unroll
                for (int h2 = 0; h2 < 2; h2++) {
                    const int r = r0 + 8 * h2;
                    *(float2*)(pre + r * LDPF + col) =
                        make_float2(acc[mt][nt][2 * h2] + cbf.x,
                                    acc[mt][nt][2 * h2 + 1] + cbf.y);
                }
            }
        }
    }
    __syncthreads();

    // ---- LayerNorm: 6 rows per warp; residual x re-read from gmem (coalesced) ----
    for (int r = w * 6; r < w * 6 + 6; r++) {
        const float* row  = pre + r * LDPF;
        const float* xrow = x + gbase + (size_t)r * DD;
        float vals[8];
        float s = 0.f, s2 = 0.f;
#pragma unroll
        for (int j = 0; j < 8; j++) {
            const float val = row[lane + 32 * j] + __ldg(xrow + lane + 32 * j);
            vals[j] = val;
            s += val; s2 = fmaf(val, val, s2);
        }
        s = warp_sum(s); s2 = warp_sum(s2);
        const float mu = s * (1.f / 256.f);
        const float var = s2 * (1.f / 256.f) - mu * mu;
        const float inv = rsqrtf(var + 1e-5f);
        float* orow = out + gbase + (size_t)r * DD;
#pragma unroll
        for (int j = 0; j < 8; j++) {
            const int c = lane + 32 * j;
            orow[c] = (vals[j] - mu) * inv * __ldg(gamma + c) + __ldg(beta + c);
        }
    }
}

extern "C" void kernel_launch(void* const* d_in, const int* in_sizes, int n_in,
                              void* d_out, int out_size)
{
    (void)in_sizes; (void)n_in; (void)out_size;
    const float* x     = (const float*)d_in[0];
    const float* Wq_w  = (const float*)d_in[1];
    const float* Wq_b  = (const float*)d_in[2];
    const float* Wk_w  = (const float*)d_in[3];
    const float* Wk_b  = (const float*)d_in[4];
    const float* Wv_w  = (const float*)d_in[5];
    const float* Wv_b  = (const float*)d_in[6];
    const float* mem_k = (const float*)d_in[7];
    const float* mem_v = (const float*)d_in[8];
    const float* fc_w  = (const float*)d_in[9];
    const float* fc_b  = (const float*)d_in[10];
    const float* gamma = (const float*)d_in[11];
    const float* beta  = (const float*)d_in[12];
    const float* alpha = (const float*)d_in[13];
    float* out = (float*)d_out;

    // 4 bf16 buffers [48][132] uints = 101376 B (pre-LN fp32 overlays kb+vb)
    const int smemBytes = 4 * MROWS * LDPH * (int)sizeof(uint32_t);
    cudaFuncSetAttribute(mtb_kernel, cudaFuncAttributeMaxDynamicSharedMemorySize, smemBytes);

    prep_kernel<<<256, 256>>>(Wq_w, Wk_w, Wv_w, fc_w);
    mtb_kernel<<<16384 / GG, 256, smemBytes>>>(x, Wq_b, Wk_b, Wv_b, mem_k, mem_v,
                                               fc_b, gamma, beta, alpha, out);
}

// round 14
// speedup vs baseline: 2.4327x; 1.5487x over previous
#include <cuda_runtime.h>
#include <cuda_bf16.h>
#include <cstdint>

// MemoryTemporalBlock — bf16 m16n8k16 everywhere, incl. MMA-based attention.
// One CTA per 4 (b,n) tiles (M=48 = 3 m16-tiles), 256 threads, ~103KB smem,
// 2 CTAs/SM. GEMMs via ldmatrix + mma; attention per (tile,head) unit:
//   S = Q·K^T (4 MMAs) -> fragment softmax -> P (bf16, C-layout == A-layout)
//   O = P·V (4 MMAs, V via ldmatrix.trans); memory bank similarly (6 MMAs,
//   mem fragments pre-packed in gmem). Masks are lane-constant predicates.
// vb pad rows (48..55) are ZEROED at staging: tau=3's V ldmatrix reads them,
// and 0 x NaN = NaN would otherwise corrupt valid rows through masked-P MMA.

#define TT 12
#define DD 256
#define GG 4
#define MROWS (GG * TT)   // 48
#define LDPH 132          // bf16 buffer stride in uints (bf16x2)
#define LDPF 260          // fp32 pre-LN stride (floats)
#define MMM 8
#define LOG2E 1.4426950408889634f

// Wfrag[mat][wn(8)][kstep(16)][ntile(4)][lane(32)] as uint2 (4 bf16)
__device__ uint2 g_Wfrag[4][8][16][4][32];
// mem_k B-fragments: [head][kstep(2)][lane]  (n = m slot, k = dk)
__device__ uint2 g_Mfrag[8][2][32];
// mem_v B-fragments: [head][ntile(4)][lane]  (n = dk col, k = m slot; k 8-15 = 0)
__device__ uint2 g_Vmfrag[8][4][32];

static __device__ __forceinline__ uint32_t pkbf(float lo, float hi) {
    __nv_bfloat162 h = __float22bfloat162_rn(make_float2(lo, hi));
    uint32_t r; memcpy(&r, &h, 4); return r;
}
static __device__ __forceinline__ float ex2(float x) {
    float r; asm("ex2.approx.f32 %0, %1;" : "=f"(r) : "f"(x)); return r;
}
static __device__ __forceinline__ void ldsm4(uint32_t* a, uint32_t saddr) {
    asm volatile("ldmatrix.sync.aligned.m8n8.x4.shared.b16 {%0,%1,%2,%3}, [%4];"
        : "=r"(a[0]), "=r"(a[1]), "=r"(a[2]), "=r"(a[3]) : "r"(saddr));
}
static __device__ __forceinline__ void ldsm2t(uint32_t* a, uint32_t saddr) {
    asm volatile("ldmatrix.sync.aligned.m8n8.x2.trans.shared.b16 {%0,%1}, [%2];"
        : "=r"(a[0]), "=r"(a[1]) : "r"(saddr));
}
static __device__ __forceinline__ void mma_bf16(float* c, const uint32_t* a,
                                                uint32_t b0, uint32_t b1) {
    asm("mma.sync.aligned.m16n8k16.row.col.f32.bf16.bf16.f32 "
        "{%0,%1,%2,%3}, {%4,%5,%6,%7}, {%8,%9}, {%0,%1,%2,%3};"
        : "+f"(c[0]), "+f"(c[1]), "+f"(c[2]), "+f"(c[3])
        : "r"(a[0]), "r"(a[1]), "r"(a[2]), "r"(a[3]), "r"(b0), "r"(b1));
}
static __device__ __forceinline__ float warp_sum(float v) {
#pragma unroll
    for (int o = 16; o; o >>= 1) v += __shfl_xor_sync(0xffffffffu, v, o);
    return v;
}
static __device__ __forceinline__ float gsum4(float v) {
    v += __shfl_xor_sync(0xffffffffu, v, 1);
    v += __shfl_xor_sync(0xffffffffu, v, 2);
    return v;
}

__global__ void prep_kernel(const float* __restrict__ wq, const float* __restrict__ wk,
                            const float* __restrict__ wv, const float* __restrict__ wf)
{
    int i = blockIdx.x * blockDim.x + threadIdx.x;   // 65536 threads
    int lane = i & 31;
    int nt   = (i >> 5) & 3;
    int kk   = (i >> 7) & 15;
    int wn   = (i >> 11) & 7;
    int mat  = i >> 14;
    const float* W = (mat == 0) ? wq : (mat == 1) ? wk : (mat == 2) ? wv : wf;
    int e = wn * 32 + nt * 8 + (lane >> 2);
    int d = kk * 16 + (lane & 3) * 2;
    uint2 v;
    v.x = pkbf(__ldg(W + e * DD + d),     __ldg(W + e * DD + d + 1));
    v.y = pkbf(__ldg(W + e * DD + d + 8), __ldg(W + e * DD + d + 9));
    g_Wfrag[mat][wn][kk][nt][lane] = v;
}

__global__ void memprep_kernel(const float* __restrict__ memk,
                               const float* __restrict__ memv)
{
    int i = blockIdx.x * blockDim.x + threadIdx.x;   // 1536 threads
    if (i < 512) {
        int lane = i & 31, kk = (i >> 5) & 1, h = i >> 6;
        int n = lane >> 2, k0 = kk * 16 + (lane & 3) * 2;
        const float* base = memk + (h * MMM + n) * 32;
        uint2 v;
        v.x = pkbf(__ldg(base + k0),     __ldg(base + k0 + 1));
        v.y = pkbf(__ldg(base + k0 + 8), __ldg(base + k0 + 9));
        g_Mfrag[h][kk][lane] = v;
    } else if (i < 1536) {
        int j = i - 512;
        int lane = j & 31, nt = (j >> 5) & 3, h = j >> 7;
        int d = nt * 8 + (lane >> 2), m0 = (lane & 3) * 2;
        uint2 v;
        v.x = pkbf(__ldg(memv + (h * MMM + m0) * 32 + d),
                   __ldg(memv + (h * MMM + m0 + 1) * 32 + d));
        v.y = 0u;   // k (m) 8-15 do not exist -> zero
        g_Vmfrag[h][nt][lane] = v;
    }
}

// GEMM sweep over K=256; A = packed bf16 smem (shared addr), 3 m-tiles (M=48).
static __device__ __forceinline__ void gemm_sweep(
    uint32_t abase, int lane,
    const uint2* __restrict__ Bp,
    float acc[3][4][4])
{
#pragma unroll
    for (int mt = 0; mt < 3; mt++)
#pragma unroll
        for (int nt = 0; nt < 4; nt++)
#pragma unroll
            for (int j = 0; j < 4; j++) acc[mt][nt][j] = 0.f;

    uint2 b0[4], b1[4];
#pragma unroll
    for (int nt = 0; nt < 4; nt++) {
        b0[nt] = __ldg(Bp + nt * 32 + lane);
        b1[nt] = __ldg(Bp + (4 + nt) * 32 + lane);
    }

    const int arow = (lane & 7) + ((lane >> 3) & 1) * 8;
    const uint32_t alane = abase + (uint32_t)(arow * LDPH * 4) + ((lane >> 4) * 16);

#pragma unroll 4
    for (int kk = 0; kk < 16; kk++) {
        uint32_t a[3][4];
#pragma unroll
        for (int mt = 0; mt < 3; mt++)
            ldsm4(a[mt], alane + (uint32_t)(mt * 16 * LDPH * 4) + (uint32_t)(kk * 32));
        uint2 bc[4];
#pragma unroll
        for (int nt = 0; nt < 4; nt++) { bc[nt] = b0[nt]; b0[nt] = b1[nt]; }
        if (kk < 14) {
#pragma unroll
            for (int nt = 0; nt < 4; nt++)
                b1[nt] = __ldg(Bp + ((kk + 2) * 4 + nt) * 32 + lane);
        }
#pragma unroll
        for (int nt = 0; nt < 4; nt++)
#pragma unroll
            for (int mt = 0; mt < 3; mt++)
                mma_bf16(acc[mt][nt], a[mt], bc[nt].x, bc[nt].y);
    }
}

// Store accumulators (+bias) as packed bf16 into a [48][LDPH] buffer.
static __device__ __forceinline__ void store_accb(
    uint32_t* __restrict__ dst, const float* __restrict__ bias,
    int w, int lane, const float acc[3][4][4])
{
#pragma unroll
    for (int nt = 0; nt < 4; nt++) {
        const int col = w * 32 + nt * 8 + 2 * (lane & 3);
        const float2 cb = __ldg((const float2*)(bias + col));
        const int cu = col >> 1;
#pragma unroll
        for (int mt = 0; mt < 3; mt++) {
            const int r0 = mt * 16 + (lane >> 2);
#pragma unroll
            for (int h2 = 0; h2 < 2; h2++) {
                const int r = r0 + 8 * h2;
                dst[r * LDPH + cu] =
                    pkbf(acc[mt][nt][2 * h2] + cb.x, acc[mt][nt][2 * h2 + 1] + cb.y);
            }
        }
    }
}

__global__ void __launch_bounds__(256, 2)
mtb_kernel(const float* __restrict__ x,
           const float* __restrict__ bq, const float* __restrict__ bk,
           const float* __restrict__ bv,
           const float* __restrict__ bf,
           const float* __restrict__ gamma, const float* __restrict__ beta,
           const float* __restrict__ alpha_p,
           float* __restrict__ out)
{
    extern __shared__ uint32_t smu[];
    uint32_t* xb = smu;                     // bf16 x            [48][132]
    uint32_t* qb = smu + 1 * MROWS * LDPH;  // bf16 Q -> attn out
    uint32_t* kb = smu + 2 * MROWS * LDPH;  // bf16 K
    uint32_t* vb = smu + 3 * MROWS * LDPH;  // bf16 V (+8 pad rows after)
    float*   pre = (float*)kb;              // fp32 pre-LN (overlays K,V after attention)

    const uint32_t qb_s = (uint32_t)__cvta_generic_to_shared(qb);
    const uint32_t kb_s = (uint32_t)__cvta_generic_to_shared(kb);
    const uint32_t vb_s = (uint32_t)__cvta_generic_to_shared(vb);
    const uint32_t xb_s = (uint32_t)__cvta_generic_to_shared(xb);

    const int tid  = threadIdx.x;
    const int w    = tid >> 5;
    const int lane = tid & 31;
    const size_t gbase = (size_t)blockIdx.x * (MROWS * DD);

    // ---- stage x as packed bf16; zero vb pad rows (read by tau=3 V ldmatrix) ----
    {
        const float4* xg = (const float4*)(x + gbase);
#pragma unroll
        for (int p = 0; p < 12; p++) {
            const int idx = p * 256 + tid;
            const int r = idx >> 6, cg = idx & 63;
            const float4 xv = xg[idx];
            xb[r * LDPH + cg * 2]     = pkbf(xv.x, xv.y);
            xb[r * LDPH + cg * 2 + 1] = pkbf(xv.z, xv.w);
        }
        for (int i = tid; i < 8 * LDPH; i += 256)
            vb[MROWS * LDPH + i] = 0u;
    }
    __syncthreads();

    // ---- sweeps: Q, K, V ----
    {
        float acc[3][4][4];
        gemm_sweep(xb_s, lane, &g_Wfrag[0][w][0][0][0], acc);
        store_accb(qb, bq, w, lane, acc);
        gemm_sweep(xb_s, lane, &g_Wfrag[1][w][0][0][0], acc);
        store_accb(kb, bk, w, lane, acc);
        gemm_sweep(xb_s, lane, &g_Wfrag[2][w][0][0][0], acc);
        store_accb(vb, bv, w, lane, acc);
    }
    __syncthreads();

    // ---- attention via MMA: 32 units (tile,head); warp w -> units 4w..4w+3 ----
    const float sl = 0.17677669529663687f * LOG2E;
    const float wl = 1.f / (1.f + __expf(-__ldg(alpha_p)));
    const float wt = 1.f - wl;

    const int g  = lane >> 2;        // C/A fragment row group
    const int q2 = (lane & 3) * 2;   // C/A fragment col base
    // lane-constant causal masks (P[t][s]: keep s <= t)
    const bool k00 = (q2     <= g);             // P0 row g,  s=q2
    const bool k01 = (q2 + 1 <= g);             // P0 row g,  s=q2+1
    const bool k12 = (q2     <= g) && (q2 < 4); // P1 row g+8, s=8+q2 (pad s<12)
    const bool k13 = (q2 + 1 <= g) && (q2 + 1 < 4);
    const int arow = (lane & 7) + ((lane >> 3) & 1) * 8;
    const int ahalf = (lane >> 4) * 16;

#pragma unroll
    for (int u = 0; u < 4; u++) {
        const int unit = w * 4 + u;
        const int tau = unit >> 3, h = unit & 7;
        const int rb = tau * TT;
        const uint32_t rowoff = (uint32_t)((rb + arow) * LDPH * 4) + (uint32_t)(h * 64 + ahalf);

        // Q A-fragments (2 k-steps), K B-fragments (2 k-steps x 2 n-tiles)
        uint32_t aq[2][4], bk2[2][4];
        ldsm4(aq[0], qb_s + rowoff);
        ldsm4(aq[1], qb_s + rowoff + 32);
        ldsm4(bk2[0], kb_s + rowoff);
        ldsm4(bk2[1], kb_s + rowoff + 32);

        // S = Q.K^T
        float S0[4] = {0.f, 0.f, 0.f, 0.f}, S1[4] = {0.f, 0.f, 0.f, 0.f};
        mma_bf16(S0, aq[0], bk2[0][0], bk2[0][2]);
        mma_bf16(S0, aq[1], bk2[1][0], bk2[1][2]);
        mma_bf16(S1, aq[0], bk2[0][1], bk2[0][3]);
        mma_bf16(S1, aq[1], bk2[1][1], bk2[1][3]);

        // softmax (no max-sub; scores O(1)); P1 rows t<8 fully masked
        const float p00 = k00 ? ex2(S0[0] * sl) : 0.f;
        const float p01 = k01 ? ex2(S0[1] * sl) : 0.f;
        const float p02 = ex2(S0[2] * sl);            // row g+8, s<=7 always kept
        const float p03 = ex2(S0[3] * sl);
        const float p12 = k12 ? ex2(S1[2] * sl) : 0.f;
        const float p13 = k13 ? ex2(S1[3] * sl) : 0.f;
        const float den_g  = gsum4(p00 + p01);
        const float den_g8 = gsum4(p02 + p03 + p12 + p13);

        // pack P -> A fragment (C layout == A layout)
        uint32_t ap[4];
        ap[0] = pkbf(p00, p01);
        ap[1] = pkbf(p02, p03);
        ap[2] = 0u;
        ap[3] = pkbf(p12, p13);

        // memory-bank scores + softmax
        const uint2 mb0 = __ldg(&g_Mfrag[h][0][lane]);
        const uint2 mb1 = __ldg(&g_Mfrag[h][1][lane]);
        float Sl[4] = {0.f, 0.f, 0.f, 0.f};
        mma_bf16(Sl, aq[0], mb0.x, mb0.y);
        mma_bf16(Sl, aq[1], mb1.x, mb1.y);
        const float pl0 = ex2(Sl[0] * sl), pl1 = ex2(Sl[1] * sl);
        const float pl2 = ex2(Sl[2] * sl), pl3 = ex2(Sl[3] * sl);
        const float dl_g  = gsum4(pl0 + pl1);
        const float dl_g8 = gsum4(pl2 + pl3);
        uint32_t apl[4];
        apl[0] = pkbf(pl0, pl1);
        apl[1] = pkbf(pl2, pl3);
        apl[2] = 0u;
        apl[3] = 0u;

        // O = P.V  and  Ol = Pl.mem_v, then gate + store
        const float it_g  = wt / den_g,  it_g8 = wt / den_g8;
        const float il_g  = wl / dl_g,   il_g8 = wl / dl_g8;
        const uint32_t vrow = vb_s + (uint32_t)((rb + arow) * LDPH * 4) + (uint32_t)(h * 64);
#pragma unroll
        for (int nt = 0; nt < 4; nt++) {
            uint32_t bv2[2];
            ldsm2t(bv2, vrow + (uint32_t)(nt * 16));
            float O[4] = {0.f, 0.f, 0.f, 0.f};
            mma_bf16(O, ap, bv2[0], bv2[1]);
            const uint2 vm = __ldg(&g_Vmfrag[h][nt][lane]);
            float Ol[4] = {0.f, 0.f, 0.f, 0.f};
            mma_bf16(Ol, apl, vm.x, vm.y);

            const int cu = h * 16 + nt * 4 + (lane & 3);
            qb[(rb + g) * LDPH + cu] =
                pkbf(O[0] * it_g + Ol[0] * il_g, O[1] * it_g + Ol[1] * il_g);
            if (g < 4)
                qb[(rb + g + 8) * LDPH + cu] =
                    pkbf(O[2] * it_g8 + Ol[2] * il_g8, O[3] * it_g8 + Ol[3] * il_g8);
        }
    }
    __syncthreads();

    // ---- sweep: fc; epilogue writes fp32 (acc+bias) into pre (overlays K/V) ----
    {
        float acc[3][4][4];
        gemm_sweep(qb_s, lane, &g_Wfrag[3][w][0][0][0], acc);
#pragma unroll
        for (int nt = 0; nt < 4; nt++) {
            const int col = w * 32 + nt * 8 + 2 * (lane & 3);
            const float2 cbf = __ldg((const float2*)(bf + col));
#pragma unroll
            for (int mt = 0; mt < 3; mt++) {
                const int r0 = mt * 16 + (lane >> 2);
#pragma unroll
                for (int h2 = 0; h2 < 2; h2++) {
                    const int r = r0 + 8 * h2;
                    *(float2*)(pre + r * LDPF + col) =
                        make_float2(acc[mt][nt][2 * h2] + cbf.x,
                                    acc[mt][nt][2 * h2 + 1] + cbf.y);
                }
            }
        }
    }
    __syncthreads();

    // ---- LayerNorm: 6 rows per warp; residual x re-read from gmem ----
    for (int r = w * 6; r < w * 6 + 6; r++) {
        const float* row  = pre + r * LDPF;
        const float* xrow = x + gbase + (size_t)r * DD;
        float vals[8];
        float s = 0.f, s2 = 0.f;
#pragma unroll
        for (int j = 0; j < 8; j++) {
            const float val = row[lane + 32 * j] + __ldg(xrow + lane + 32 * j);
            vals[j] = val;
            s += val; s2 = fmaf(val, val, s2);
        }
        s = warp_sum(s); s2 = warp_sum(s2);
        const float mu = s * (1.f / 256.f);
        const float var = s2 * (1.f / 256.f) - mu * mu;
        const float inv = rsqrtf(var + 1e-5f);
        float* orow = out + gbase + (size_t)r * DD;
#pragma unroll
        for (int j = 0; j < 8; j++) {
            const int c = lane + 32 * j;
            orow[c] = (vals[j] - mu) * inv * __ldg(gamma + c) + __ldg(beta + c);
        }
    }
}

extern "C" void kernel_launch(void* const* d_in, const int* in_sizes, int n_in,
                              void* d_out, int out_size)
{
    (void)in_sizes; (void)n_in; (void)out_size;
    const float* x     = (const float*)d_in[0];
    const float* Wq_w  = (const float*)d_in[1];
    const float* Wq_b  = (const float*)d_in[2];
    const float* Wk_w  = (const float*)d_in[3];
    const float* Wk_b  = (const float*)d_in[4];
    const float* Wv_w  = (const float*)d_in[5];
    const float* Wv_b  = (const float*)d_in[6];
    const float* mem_k = (const float*)d_in[7];
    const float* mem_v = (const float*)d_in[8];
    const float* fc_w  = (const float*)d_in[9];
    const float* fc_b  = (const float*)d_in[10];
    const float* gamma = (const float*)d_in[11];
    const float* beta  = (const float*)d_in[12];
    const float* alpha = (const float*)d_in[13];
    float* out = (float*)d_out;

    // 4 bf16 buffers [48][132] uints + 8 pad rows (ldmatrix overrun at tau=3)
    const int smemBytes = (4 * MROWS + 8) * LDPH * (int)sizeof(uint32_t);
    cudaFuncSetAttribute(mtb_kernel, cudaFuncAttributeMaxDynamicSharedMemorySize, smemBytes);

    prep_kernel<<<256, 256>>>(Wq_w, Wk_w, Wv_w, fc_w);
    memprep_kernel<<<6, 256>>>(mem_k, mem_v);
    mtb_kernel<<<16384 / GG, 256, smemBytes>>>(x, Wq_b, Wk_b, Wv_b,
                                               fc_b, gamma, beta, alpha, out);
}